// round 5
// baseline (speedup 1.0000x reference)
#include <cuda_runtime.h>

#define BB 8
#define NN 16384
#define DD 768
#define RR 3

// ---------------- scratch (device globals; no allocation) ----------------
__device__ float g_feat[BB*RR*NN];        // planar (B,R,128,128), includes bias
__device__ float g_partial[2048*RR];      // per-block partial sums (pre-bias)
__device__ float g_G[BB*4];               // gate weights
__device__ float g_c0[BB*RR*128*128];
__device__ float g_c1[BB*RR*64*64];
__device__ float g_c2[BB*RR*32*32];
__device__ float g_c3[BB*RR*16*16];

// ------ kernel 1: feat = x @ Wd + bd (planar) + partials; regs-resident W -
__global__ __launch_bounds__(256) void k_proj(const float* __restrict__ x,
                                              const float* __restrict__ Wd,
                                              const float* __restrict__ bd) {
    __shared__ float4 sW4[576];           // Wd (768,3) as float4
    __shared__ float wp[8][3];
    int t = threadIdx.x;
    const float4* Wd4 = (const float4*)Wd;
    for (int i = t; i < 576; i += 256) sW4[i] = Wd4[i];
    __syncthreads();
    int warp = t >> 5, lane = t & 31;
    // preload this lane's weight slice into registers (once per 8 rows)
    float4 w[6][3];
#pragma unroll
    for (int i = 0; i < 6; i++) {
        int base = 3 * (i*32 + lane);
        w[i][0] = sW4[base]; w[i][1] = sW4[base+1]; w[i][2] = sW4[base+2];
    }
    long row0 = (long)blockIdx.x * 64 + warp * 8;
    float p0 = 0.f, p1 = 0.f, p2 = 0.f;
    for (int rr = 0; rr < 8; rr++) {
        long row = row0 + rr;
        const float4* xp = (const float4*)(x + row * DD);
        float4 v[6];
#pragma unroll
        for (int i = 0; i < 6; i++) v[i] = xp[i*32 + lane];
        float a0 = 0.f, a1 = 0.f, a2 = 0.f;
#pragma unroll
        for (int i = 0; i < 6; i++) {
            float4 w0 = w[i][0], w1 = w[i][1], w2 = w[i][2];
            a0 += v[i].x*w0.x; a1 += v[i].x*w0.y; a2 += v[i].x*w0.z;
            a0 += v[i].y*w0.w; a1 += v[i].y*w1.x; a2 += v[i].y*w1.y;
            a0 += v[i].z*w1.z; a1 += v[i].z*w1.w; a2 += v[i].z*w2.x;
            a0 += v[i].w*w2.y; a1 += v[i].w*w2.z; a2 += v[i].w*w2.w;
        }
#pragma unroll
        for (int o = 16; o; o >>= 1) {
            a0 += __shfl_xor_sync(0xffffffffu, a0, o);
            a1 += __shfl_xor_sync(0xffffffffu, a1, o);
            a2 += __shfl_xor_sync(0xffffffffu, a2, o);
        }
        if (lane == 0) {
            int b = (int)(row >> 14), n = (int)(row & 16383);
            g_feat[(b*3 + 0)*NN + n] = a0 + bd[0];
            g_feat[(b*3 + 1)*NN + n] = a1 + bd[1];
            g_feat[(b*3 + 2)*NN + n] = a2 + bd[2];
            p0 += a0; p1 += a1; p2 += a2;
        }
    }
    if (lane == 0) { wp[warp][0] = p0; wp[warp][1] = p1; wp[warp][2] = p2; }
    __syncthreads();
    if (t == 0) {   // deterministic fixed-order block partial
        float q0 = 0.f, q1 = 0.f, q2 = 0.f;
        for (int w2 = 0; w2 < 8; w2++) { q0 += wp[w2][0]; q1 += wp[w2][1]; q2 += wp[w2][2]; }
        g_partial[blockIdx.x*3+0] = q0;
        g_partial[blockIdx.x*3+1] = q1;
        g_partial[blockIdx.x*3+2] = q2;
    }
}

// ---------------- kernel 2: mean + gating (noisy top-2 softmax) -----------
__global__ void k_gate(const float* __restrict__ noise,
                       const float* __restrict__ bd,
                       const float* __restrict__ Wg,
                       const float* __restrict__ Wn) {
    __shared__ float s_xa[24];
    int t = threadIdx.x;
    int c = t >> 5, lane = t & 31;
    if (c < 24) {                      // c = b*3 + r ; 256 blocks per batch
        int b = c / 3, r = c - b*3;
        float s = 0.f;
        for (int k = lane; k < 256; k += 32)
            s += g_partial[(b*256 + k)*3 + r];
#pragma unroll
        for (int o = 16; o; o >>= 1) s += __shfl_xor_sync(0xffffffffu, s, o);
        if (lane == 0) s_xa[c] = s * (1.0f/16384.0f) + bd[r];
    }
    __syncthreads();
    if (t < 8) {
        int b = t;
        float x0 = s_xa[b*3], x1 = s_xa[b*3+1], x2 = s_xa[b*3+2];
        float hl[4];
#pragma unroll
        for (int e = 0; e < 4; e++) {
            float hg = x0*Wg[e] + x1*Wg[4+e] + x2*Wg[8+e];
            float z  = x0*Wn[e] + x1*Wn[4+e] + x2*Wn[8+e];
            float sp = fmaxf(z, 0.f) + log1pf(expf(-fabsf(z)));   // softplus
            hl[e] = hg + noise[b*4+e]*sp;
        }
        int i1 = 0;
        for (int e = 1; e < 4; e++) if (hl[e] > hl[i1]) i1 = e;
        int i2 = -1;
        for (int e = 0; e < 4; e++) { if (e == i1) continue; if (i2 < 0 || hl[e] > hl[i2]) i2 = e; }
        float m  = hl[i1];
        float e2 = expf(hl[i2] - m);
        float inv = 1.f / (1.f + e2);
#pragma unroll
        for (int e = 0; e < 4; e++) g_G[b*4+e] = 0.f;
        g_G[b*4+i1] = inv;
        g_G[b*4+i2] = e2*inv;
    }
}

// ---------------- bilinear helpers (half-pixel, edge-clamped) -------------
__device__ __forceinline__ void lco(int i, int Sin, float scale,
                                    int& i0, int& i1, float& w) {
    float c = (i + 0.5f) * scale - 0.5f;
    float f = floorf(c);
    w = c - f;
    i0 = (int)f; i1 = i0 + 1;
    if (i0 < 0) i0 = 0;
    if (i1 > Sin - 1) i1 = Sin - 1;
}

// downsample plane (128x128) -> S at (y,x), on the fly
__device__ __forceinline__ float dval(const float* __restrict__ p, int S, int y, int x) {
    float scale = 128.0f / (float)S;
    int y0, y1, x0, x1; float wy, wx;
    lco(y, 128, scale, y0, y1, wy);
    lco(x, 128, scale, x0, x1, wx);
    float v00 = p[(y0<<7)+x0], v01 = p[(y0<<7)+x1];
    float v10 = p[(y1<<7)+x0], v11 = p[(y1<<7)+x1];
    return (1.f-wy)*((1.f-wx)*v00 + wx*v01) + wy*((1.f-wx)*v10 + wx*v11);
}

// ---------------- kernel 3: fused downsample + depthwise 3x3 --------------
__global__ void k_conv(const float* __restrict__ dwk, const float* __restrict__ dwb) {
    int idx = blockIdx.x * 256 + threadIdx.x;
    int S, local; float* out;
    if      (idx < 393216) { S = 128; out = g_c0; local = idx; }
    else if (idx < 491520) { S = 64;  out = g_c1; local = idx - 393216; }
    else if (idx < 516096) { S = 32;  out = g_c2; local = idx - 491520; }
    else if (idx < 522240) { S = 16;  out = g_c3; local = idx - 516096; }
    else return;
    int br = local / (S*S); int pix = local - br*S*S;
    int y = pix / S, x = pix - y*S;
    int r = br % 3;
    const float* plane = g_feat + br * NN;
    float acc = dwb[r];
#pragma unroll
    for (int dy = 0; dy < 3; dy++) {
        int yy = y + dy - 1; if (yy < 0 || yy >= S) continue;
#pragma unroll
        for (int dx = 0; dx < 3; dx++) {
            int xx = x + dx - 1; if (xx < 0 || xx >= S) continue;
            float v = (S == 128) ? plane[(yy<<7)+xx] : dval(plane, S, yy, xx);
            acc += v * dwk[r*9 + dy*3 + dx];
        }
    }
    out[local] = acc;
}

// upsample S -> 128 at (y,x)
__device__ __forceinline__ float bilerp_up(const float* __restrict__ p, int S, int y, int x) {
    float scale = (float)S / 128.0f;
    int y0, y1, x0, x1; float wy, wx;
    lco(y, S, scale, y0, y1, wy);
    lco(x, S, scale, x0, x1, wx);
    float v00 = p[y0*S + x0], v01 = p[y0*S + x1];
    float v10 = p[y1*S + x0], v11 = p[y1*S + x1];
    return (1.f-wy)*((1.f-wx)*v00 + wx*v01) + wy*((1.f-wx)*v10 + wx*v11);
}

// ------ kernel 4: out = x + mixed @ Wu + bu ; thread-owns-q, regs weights -
__global__ __launch_bounds__(192) void k_final(const float* __restrict__ x,
                                               const float* __restrict__ Wu,
                                               const float* __restrict__ bu,
                                               float* __restrict__ out) {
    __shared__ float s_m[64][3];
    int t = threadIdx.x;
    long row0 = (long)blockIdx.x * 64;
    int b = (int)(row0 >> 14);
    int n0 = (int)(row0 & 16383);
    // phase 1: 192 threads compute the 64x3 mixed values for this row block
    {
        int rl = t / 3, ch = t - rl*3;
        int n = n0 + rl; int yy = n >> 7, xx = n & 127;
        int br = b*3 + ch;
        float G0 = g_G[b*4+0], G1 = g_G[b*4+1], G2 = g_G[b*4+2], G3 = g_G[b*4+3];
        float m = G0 * g_c0[br*16384 + n]
                + G1 * bilerp_up(g_c1 + br*4096, 64, yy, xx)
                + G2 * bilerp_up(g_c2 + br*1024, 32, yy, xx)
                + G3 * bilerp_up(g_c3 + br*256,  16, yy, xx);
        s_m[rl][ch] = m;
    }
    __syncthreads();
    // phase 2: thread owns d-chunk q; weights in registers; loop rows
    int q = t;                                     // 0..191 float4s of 768
    const float4* Wu4 = (const float4*)Wu;
    float4 w0 = Wu4[q], w1 = Wu4[192 + q], w2 = Wu4[384 + q];
    float4 bb = ((const float4*)bu)[q];
    const float4* xp = (const float4*)x + (int)row0 * 192 + q;
    float4*       op = (float4*)out     + (int)row0 * 192 + q;
#pragma unroll 4
    for (int rl = 0; rl < 64; rl++) {
        float4 v = xp[rl * 192];
        float m0 = s_m[rl][0], m1 = s_m[rl][1], m2 = s_m[rl][2];
        float4 o;
        o.x = v.x + m0*w0.x + m1*w1.x + m2*w2.x + bb.x;
        o.y = v.y + m0*w0.y + m1*w1.y + m2*w2.y + bb.y;
        o.z = v.z + m0*w0.z + m1*w1.z + m2*w2.z + bb.z;
        o.w = v.w + m0*w0.w + m1*w1.w + m2*w2.w + bb.w;
        op[rl * 192] = o;
    }
}

// ---------------- launch --------------------------------------------------
extern "C" void kernel_launch(void* const* d_in, const int* in_sizes, int n_in,
                              void* d_out, int out_size) {
    const float* x     = (const float*)d_in[0];
    const float* noise = (const float*)d_in[1];
    const float* Wd    = (const float*)d_in[2];
    const float* bd    = (const float*)d_in[3];
    const float* Wu    = (const float*)d_in[4];
    const float* bu    = (const float*)d_in[5];
    const float* Wg    = (const float*)d_in[6];
    const float* Wn    = (const float*)d_in[7];
    const float* dwk   = (const float*)d_in[8];
    const float* dwb   = (const float*)d_in[9];
    float* out = (float*)d_out;

    k_proj <<<2048, 256>>>(x, Wd, bd);
    k_gate <<<1, 768>>>(noise, bd, Wg, Wn);
    k_conv <<<2040, 256>>>(dwk, dwb);
    k_final<<<2048, 192>>>(x, Wu, bu, out);
}